// round 14
// baseline (speedup 1.0000x reference)
#include <cuda_runtime.h>
#include <cuda_bf16.h>
#include <math.h>
#include <stdint.h>

static constexpr int NB = 512;   // batch
static constexpr int NC = 24;    // conv channels (FS)
static constexpr int NH = 256;   // hidden
static constexpr int NT = 20;    // gmlp tiles per batch (32 rows each, 625 pair rows)

// ---------------- scratch (device globals; allocation is forbidden) ----------------
__device__ float g_y1[(size_t)NB * NC * 40 * 40];
__device__ float g_y2[(size_t)NB * NC * 20 * 20];
__device__ float g_y3[(size_t)NB * NC * 10 * 10];
__device__ float g_y4[(size_t)NB * NC * 5 * 5];
__device__ float g_scale[4 * NC];
__device__ float g_shift[4 * NC];
__device__ float g_bnp[24 * 32 * 2];                 // fp32 partial sums (fixed-order, deterministic)
__device__ float g_A[(size_t)NB * 25 * NH];          // W1[:,0:26]  @ obj_i
__device__ float g_Bt[(size_t)NB * 25 * NH];         // W1[:,26:52] @ obj_k
__device__ float g_Ct[(size_t)NB * NH];              // W1[:,52:63] @ q + b1
__device__ float g_xg[(size_t)NT * NB * NH];         // per-tile pair-sum partials
__device__ __align__(16) uint32_t g_whi[3 * 32768];  // weights bf16-hi pairs, [L][ks][n][j]
__device__ __align__(16) uint32_t g_wlo[3 * 32768];  // bf16-lo pairs

// ---------------- helpers ----------------
__device__ __forceinline__ void split2(float v0, float v1, uint32_t& hw, uint32_t& lw) {
    __nv_bfloat16 h0 = __float2bfloat16(v0), h1 = __float2bfloat16(v1);
    float l0 = v0 - __bfloat162float(h0);
    float l1 = v1 - __bfloat162float(h1);
    __nv_bfloat16 e0 = __float2bfloat16(l0), e1 = __float2bfloat16(l1);
    hw = (uint32_t)__bfloat16_as_ushort(h0) | ((uint32_t)__bfloat16_as_ushort(h1) << 16);
    lw = (uint32_t)__bfloat16_as_ushort(e0) | ((uint32_t)__bfloat16_as_ushort(e1) << 16);
}

__device__ __forceinline__ void mma16816(float* c, const uint32_t* a, uint32_t b0, uint32_t b1) {
    asm volatile("mma.sync.aligned.m16n8k16.row.col.f32.bf16.bf16.f32 "
                 "{%0,%1,%2,%3}, {%4,%5,%6,%7}, {%8,%9}, {%0,%1,%2,%3};\n"
                 : "+f"(c[0]), "+f"(c[1]), "+f"(c[2]), "+f"(c[3])
                 : "r"(a[0]), "r"(a[1]), "r"(a[2]), "r"(a[3]), "r"(b0), "r"(b1));
}

__device__ __forceinline__ uint32_t cvta_s(const void* p) {
    return (uint32_t)__cvta_generic_to_shared(p);
}

__device__ __forceinline__ void ldsm4(uint32_t* r, uint32_t a) {
    asm volatile("ldmatrix.sync.aligned.m8n8.x4.shared.b16 {%0,%1,%2,%3}, [%4];"
                 : "=r"(r[0]), "=r"(r[1]), "=r"(r[2]), "=r"(r[3]) : "r"(a));
}

// ---------------- conv (stride 2, pad 1) + bias + relu, 2 output px / thread ----------------
template <int CIN, bool AFFINE>
__global__ void conv_bn_relu_w2(
    const float* __restrict__ x, const float* __restrict__ w,
    const float* __restrict__ bias,
    const float* __restrict__ scl, const float* __restrict__ shf,
    float* __restrict__ y, int Hin, int Hout)
{
    __shared__ float wsm[CIN * 9 * NC];   // [ci][r][s][c]
    __shared__ float bsm[NC];
    __shared__ float ssm[CIN], hsm[CIN];
    for (int t = threadIdx.x; t < CIN * 9 * NC; t += blockDim.x) {
        int c = t % NC, rest = t / NC;
        wsm[t] = w[c * CIN * 9 + rest];
    }
    if (threadIdx.x < NC && threadIdx.x < blockDim.x) bsm[threadIdx.x] = bias[threadIdx.x];
    if (threadIdx.x < CIN) {
        ssm[threadIdx.x] = AFFINE ? scl[threadIdx.x] : 1.f;
        hsm[threadIdx.x] = AFFINE ? shf[threadIdx.x] : 0.f;
    }
    __syncthreads();

    int W2 = Hout >> 1;
    int tix = blockIdx.x * blockDim.x + threadIdx.x;   // over NB*Hout*W2
    if (tix >= NB * Hout * W2) return;
    int gx = tix % W2;
    int t2 = tix / W2;
    int oh = t2 % Hout;
    int b  = t2 / Hout;
    int ow0  = gx * 2;
    int col0 = 4 * gx - 1;

    float acc0[NC], acc1[NC];
#pragma unroll
    for (int c = 0; c < NC; c++) { acc0[c] = bsm[c]; acc1[c] = bsm[c]; }

    const float* xb = x + (size_t)b * CIN * Hin * Hin;
    for (int ci = 0; ci < CIN; ci++) {
        const float* xc = xb + (size_t)ci * Hin * Hin;
        float a = ssm[ci], sh = hsm[ci];
#pragma unroll
        for (int r = 0; r < 3; r++) {
            int ih = 2 * oh - 1 + r;
            float v[5];
            if ((unsigned)ih < (unsigned)Hin) {
                const float* xr = xc + ih * Hin;
                float4 v4 = *(const float4*)(xr + col0 + 1);
                v[0] = (gx > 0) ? fmaf(xr[col0], a, sh) : 0.f;   // pad col -1 -> 0
                v[1] = fmaf(v4.x, a, sh);
                v[2] = fmaf(v4.y, a, sh);
                v[3] = fmaf(v4.z, a, sh);
                v[4] = fmaf(v4.w, a, sh);
            } else {
                v[0] = v[1] = v[2] = v[3] = v[4] = 0.f;
            }
#pragma unroll
            for (int s = 0; s < 3; s++) {
                float p0 = v[s];
                float p1 = v[s + 2];
                const float4* wp4 = (const float4*)&wsm[(ci * 9 + r * 3 + s) * NC];
#pragma unroll
                for (int q = 0; q < 6; q++) {
                    float4 w4 = wp4[q];
                    acc0[4*q+0] = fmaf(p0, w4.x, acc0[4*q+0]);
                    acc0[4*q+1] = fmaf(p0, w4.y, acc0[4*q+1]);
                    acc0[4*q+2] = fmaf(p0, w4.z, acc0[4*q+2]);
                    acc0[4*q+3] = fmaf(p0, w4.w, acc0[4*q+3]);
                    acc1[4*q+0] = fmaf(p1, w4.x, acc1[4*q+0]);
                    acc1[4*q+1] = fmaf(p1, w4.y, acc1[4*q+1]);
                    acc1[4*q+2] = fmaf(p1, w4.z, acc1[4*q+2]);
                    acc1[4*q+3] = fmaf(p1, w4.w, acc1[4*q+3]);
                }
            }
        }
    }
    int HW = Hout * Hout;
    float* yb = y + (size_t)b * NC * HW + oh * Hout + ow0;
#pragma unroll
    for (int c = 0; c < NC; c++) {
        float2 o = make_float2(fmaxf(acc0[c], 0.f), fmaxf(acc1[c], 0.f));
        *(float2*)(yb + (size_t)c * HW) = o;
    }
}

// ---------------- scalar conv (used for conv4, Hout=5 odd) ----------------
template <int CIN, bool AFFINE>
__global__ void conv_bn_relu(const float* __restrict__ x, const float* __restrict__ w,
                             const float* __restrict__ bias,
                             const float* __restrict__ scl, const float* __restrict__ shf,
                             float* __restrict__ y, int Hin, int Hout)
{
    __shared__ float wsm[CIN * 9 * NC];
    __shared__ float bsm[NC];
    __shared__ float ssm[CIN], hsm[CIN];
    for (int t = threadIdx.x; t < CIN * 9 * NC; t += blockDim.x) {
        int c = t % NC, rest = t / NC;
        wsm[t] = w[c * CIN * 9 + rest];
    }
    if (threadIdx.x < NC) bsm[threadIdx.x] = bias[threadIdx.x];
    if (threadIdx.x < CIN) {
        ssm[threadIdx.x] = AFFINE ? scl[threadIdx.x] : 1.f;
        hsm[threadIdx.x] = AFFINE ? shf[threadIdx.x] : 0.f;
    }
    __syncthreads();

    int pix = blockIdx.x * blockDim.x + threadIdx.x;
    if (pix >= NB * Hout * Hout) return;
    int ow = pix % Hout;
    int t2 = pix / Hout;
    int oh = t2 % Hout;
    int b  = t2 / Hout;

    float acc[NC];
#pragma unroll
    for (int c = 0; c < NC; c++) acc[c] = bsm[c];

    const float* xb = x + (size_t)b * CIN * Hin * Hin;
    for (int ci = 0; ci < CIN; ci++) {
        const float* xc = xb + (size_t)ci * Hin * Hin;
        float a = ssm[ci], sh = hsm[ci];
#pragma unroll
        for (int r = 0; r < 3; r++) {
            int ih = 2 * oh - 1 + r;
            if ((unsigned)ih >= (unsigned)Hin) continue;
#pragma unroll
            for (int s = 0; s < 3; s++) {
                int iw = 2 * ow - 1 + s;
                if ((unsigned)iw >= (unsigned)Hin) continue;
                float v = fmaf(xc[ih * Hin + iw], a, sh);
                const float4* wp4 = (const float4*)&wsm[(ci * 9 + r * 3 + s) * NC];
#pragma unroll
                for (int q = 0; q < 6; q++) {
                    float4 w4 = wp4[q];
                    acc[4*q+0] = fmaf(v, w4.x, acc[4*q+0]);
                    acc[4*q+1] = fmaf(v, w4.y, acc[4*q+1]);
                    acc[4*q+2] = fmaf(v, w4.z, acc[4*q+2]);
                    acc[4*q+3] = fmaf(v, w4.w, acc[4*q+3]);
                }
            }
        }
    }
    float* yb = y + (size_t)b * NC * Hout * Hout + oh * Hout + ow;
    int HW = Hout * Hout;
#pragma unroll
    for (int c = 0; c < NC; c++) yb[(size_t)c * HW] = fmaxf(acc[c], 0.f);
}

// ---------------- BN stats: two-stage, fp32 accumulation (fixed order, deterministic) ------
__global__ void bn_part(const float* __restrict__ y, float* __restrict__ part, int HW)
{
    int c = blockIdx.x, s = blockIdx.y;
    float sum = 0.f, sq = 0.f;
    if ((HW & 3) == 0) {
        int HW4 = HW >> 2;
        for (int b = s * 16; b < s * 16 + 16; b++) {
            const float4* p = (const float4*)(y + ((size_t)b * NC + c) * HW);
            for (int i = threadIdx.x; i < HW4; i += 256) {
                float4 v = p[i];
                sum += (v.x + v.y) + (v.z + v.w);
                float q2 = fmaf(v.x, v.x, v.y * v.y);
                float q3 = fmaf(v.z, v.z, v.w * v.w);
                sq += q2 + q3;
            }
        }
    } else {
        for (int b = s * 16; b < s * 16 + 16; b++) {
            const float* p = y + ((size_t)b * NC + c) * HW;
            for (int hw = threadIdx.x; hw < HW; hw += 256) {
                float v = p[hw];
                sum += v;
                sq = fmaf(v, v, sq);
            }
        }
    }
    __shared__ float rs[256], rq[256];
    rs[threadIdx.x] = sum; rq[threadIdx.x] = sq;
    __syncthreads();
    for (int off = 128; off; off >>= 1) {
        if (threadIdx.x < off) { rs[threadIdx.x] += rs[threadIdx.x + off];
                                 rq[threadIdx.x] += rq[threadIdx.x + off]; }
        __syncthreads();
    }
    if (threadIdx.x == 0) {
        part[(c * 32 + s) * 2 + 0] = rs[0];
        part[(c * 32 + s) * 2 + 1] = rq[0];
    }
}

__global__ void bn_fin(const float* __restrict__ part,
                       const float* __restrict__ gamma, const float* __restrict__ beta,
                       float* __restrict__ scale, float* __restrict__ shift, int HW)
{
    int c = blockIdx.x, l = threadIdx.x;   // 32 threads
    double s = (double)part[(c * 32 + l) * 2 + 0];
    double q = (double)part[(c * 32 + l) * 2 + 1];
#pragma unroll
    for (int off = 16; off; off >>= 1) {
        s += __shfl_down_sync(0xffffffffu, s, off);
        q += __shfl_down_sync(0xffffffffu, q, off);
    }
    if (l == 0) {
        double n = (double)NB * HW;
        double mean = s / n;
        double var  = q / n - mean * mean;
        float inv = gamma[c] * rsqrtf((float)var + 1e-5f);
        scale[c] = inv;
        shift[c] = beta[c] - (float)mean * inv;
    }
}

// ---------------- weight presplit: fp32 [n][k] -> bf16 hi/lo pairs [ks][n][j] ----------------
__global__ void wsplit(const float* __restrict__ g2w, const float* __restrict__ g3w,
                       const float* __restrict__ g4w,
                       uint32_t* __restrict__ Whi, uint32_t* __restrict__ Wlo)
{
    int q = blockIdx.x * 256 + threadIdx.x;   // pair index over 3*32768
    if (q >= 3 * 32768) return;
    int L = q >> 15, r = q & 32767;
    int n = r >> 7, k2 = r & 127;
    const float* src = (L == 0) ? g2w : (L == 1) ? g3w : g4w;
    float2 v = *(const float2*)(src + (size_t)n * 256 + 2 * k2);
    uint32_t hw, lw;
    split2(v.x, v.y, hw, lw);
    int dst = L * 32768 + (k2 >> 3) * 2048 + n * 8 + (k2 & 7);
    Whi[dst] = hw; Wlo[dst] = lw;
}

// ---------------- layer-1 factorization terms ----------------
__global__ void ab_terms(const float* __restrict__ y4,
                         const float* __restrict__ scl, const float* __restrict__ shf,
                         const float* __restrict__ g1w,
                         float* __restrict__ A, float* __restrict__ Bm)
{
    int bi = blockIdx.x;            // b*25+i
    int i  = bi % 25;
    int b  = bi / 25;
    __shared__ float obj[26];
    if (threadIdx.x < NC) {
        float v = y4[((size_t)b * NC + threadIdx.x) * 25 + i];
        obj[threadIdx.x] = fmaf(v, scl[threadIdx.x], shf[threadIdx.x]);
    }
    if (threadIdx.x == 24) obj[24] = (float)(i / 5 - 2) * 0.5f;
    if (threadIdx.x == 25) obj[25] = (float)(i % 5 - 2) * 0.5f;
    __syncthreads();
    int n = threadIdx.x;
    const float* wr = g1w + n * 63;
    float a = 0.f, bb = 0.f;
#pragma unroll
    for (int c = 0; c < 26; c++) {
        float o = obj[c];
        a  = fmaf(o, wr[c],      a);
        bb = fmaf(o, wr[26 + c], bb);
    }
    A [(size_t)bi * NH + n] = a;
    Bm[(size_t)bi * NH + n] = bb;
}

__global__ void c_term(const float* __restrict__ qst, const float* __restrict__ g1w,
                       const float* __restrict__ g1b, float* __restrict__ Cm)
{
    int b = blockIdx.x, n = threadIdx.x;
    float acc = g1b[n];
    const float* wr = g1w + n * 63 + 52;
#pragma unroll
    for (int j = 0; j < 11; j++) acc = fmaf(qst[j * NB + b], wr[j], acc);
    Cm[(size_t)b * NH + n] = acc;
}

// ---------------- fused g-MLP on tensor cores (bf16 hi/lo split, fp32 acc) ----------------
// M=32 tile, 3 CTAs/SM. SMEM u32 layout:
//   [0,4096)       hp_hi : h bf16-hi pairs, [row 32][col 128] col ^= (row&7)<<2
//   [4096,8192)    hp_lo
//   [8192,16384)   wsm   : 2 bufs x 16KB; per buf (uint4): hi [j2*256+n] at [0,512), lo [512,1024)
//   [16384,17152)  bias  : 3 x 256 f32
//   [17152,17408)  Cs
//   [17408,17920)  red
static constexpr int GMLP_SMEM = 17920 * 4;   // 71680 B -> 3 CTAs/SM

__device__ __forceinline__ void gemm256(
    uint32_t* __restrict__ hp_hi, uint32_t* __restrict__ hp_lo, uint4* __restrict__ wsm4,
    const uint32_t* __restrict__ wh, const uint32_t* __restrict__ wl,
    float acc[8][4], int tid, int wm, int wn, int lane)
{
    // thread tid owns weight row n = tid; 8 k-pairs per k-step (2 uint4 each of hi/lo)
    const uint4* wh4 = (const uint4*)wh;
    const uint4* wl4 = (const uint4*)wl;
    uint4 ph0 = wh4[tid * 2],     ph1 = wh4[tid * 2 + 1];
    uint4 pl0 = wl4[tid * 2],     pl1 = wl4[tid * 2 + 1];

    // per-lane LDSM address components (one m16 tile per warp)
    int mat = lane >> 3, rr = lane & 7;
    int m2 = mat >> 1;                     // k-half of the A matrix this lane addresses
    int rowA = wm * 16 + (mat & 1) * 8 + rr;
    uint32_t a_hi_base = cvta_s(hp_hi) + rowA * 512;   // 128 u32 = 512 B per row
    uint32_t a_lo_base = cvta_s(hp_lo) + rowA * 512;

    int j2b = (lane >> 3) & 1, nbq = lane >> 4, rb = lane & 7;
    uint32_t b_off[4];
#pragma unroll
    for (int q = 0; q < 4; q++) {
        int nb = wn * 8 + 2 * q + nbq;
        b_off[q] = (uint32_t)(j2b * 256 + nb * 8 + rb) * 16;   // bytes within buffer
    }
    uint32_t wbase = cvta_s(wsm4);

#pragma unroll 1
    for (int ks = 0; ks < 16; ks++) {
        uint4* wb = wsm4 + (ks & 1) * 1024;
        wb[        tid] = ph0;     // hi, j2=0
        wb[ 256 + tid] = ph1;      // hi, j2=1
        wb[ 512 + tid] = pl0;      // lo, j2=0
        wb[ 768 + tid] = pl1;      // lo, j2=1
        __syncthreads();
        if (ks < 15) {
            ph0 = wh4[(ks + 1) * 512 + tid * 2]; ph1 = wh4[(ks + 1) * 512 + tid * 2 + 1];
            pl0 = wl4[(ks + 1) * 512 + tid * 2]; pl1 = wl4[(ks + 1) * 512 + tid * 2 + 1];
        }
        // A fragments via ldmatrix (unit index = (ks*2 + m2) ^ rr, 16B units)
        uint32_t ahi[4], alo[4];
        uint32_t un = (uint32_t)(((ks * 2 + m2) ^ rr) * 16);
        ldsm4(ahi, a_hi_base + un);
        ldsm4(alo, a_lo_base + un);
        uint32_t bufb = wbase + (uint32_t)(ks & 1) * 16384;
#pragma unroll
        for (int q = 0; q < 4; q++) {
            uint32_t bh[4], bl[4];
            ldsm4(bh, bufb + b_off[q]);            // (b0,b1) of n-blocks 2q, 2q+1 (hi)
            ldsm4(bl, bufb + 8192 + b_off[q]);     // same (lo)
            mma16816(acc[2 * q],     ahi, bh[0], bh[1]);
            mma16816(acc[2 * q],     ahi, bl[0], bl[1]);
            mma16816(acc[2 * q],     alo, bh[0], bh[1]);
            mma16816(acc[2 * q + 1], ahi, bh[2], bh[3]);
            mma16816(acc[2 * q + 1], ahi, bl[2], bl[3]);
            mma16816(acc[2 * q + 1], alo, bh[2], bh[3]);
        }
    }
    __syncthreads();   // all hp reads complete -> safe to overwrite hp
}

__global__ __launch_bounds__(256, 3) void gmlp_mma(
    const float* __restrict__ A, const float* __restrict__ Bm, const float* __restrict__ Cm,
    const uint32_t* __restrict__ Whi, const uint32_t* __restrict__ Wlo,
    const float* __restrict__ g2b, const float* __restrict__ g3b, const float* __restrict__ g4b,
    float* __restrict__ xg)
{
    extern __shared__ uint32_t smu[];
    uint32_t* hp_hi = smu;
    uint32_t* hp_lo = smu + 4096;
    uint4*    wsm4  = (uint4*)(smu + 8192);
    float* bias = (float*)(smu + 16384);
    float* Cs   = (float*)(smu + 17152);
    float* red  = (float*)(smu + 17408);

    int tid = threadIdx.x;
    int lane = tid & 31, w = tid >> 5;
    int wm = w >> 2, wn = w & 3;
    int group = lane >> 2, tig = lane & 3;
    int b = blockIdx.x / NT;
    int tile = blockIdx.x % NT;

    bias[tid] = g2b[tid]; bias[256 + tid] = g3b[tid]; bias[512 + tid] = g4b[tid];
    Cs[tid] = Cm[(size_t)b * NH + tid];
    __syncthreads();

    // ---- build h1 = relu(A[i] + B[k] + C) for rows tile*32 .. +31 (pad rows -> 0) ----
    const float* Ab = A  + (size_t)b * 25 * NH;
    const float* Bb = Bm + (size_t)b * 25 * NH;
    int rhalf = tid >> 7;
    int cp = tid & 127;
#pragma unroll 4
    for (int q0 = 0; q0 < 32; q0 += 2) {
        int row = q0 + rhalf;
        int gr = tile * 32 + row;
        float v0 = 0.f, v1 = 0.f;
        if (gr < 625) {
            int i = gr % 25, k = gr / 25;
            float2 av = *(const float2*)(Ab + i * NH + 2 * cp);
            float2 bv = *(const float2*)(Bb + k * NH + 2 * cp);
            float2 cv = *(const float2*)(Cs + 2 * cp);
            v0 = fmaxf(av.x + bv.x + cv.x, 0.f);
            v1 = fmaxf(av.y + bv.y + cv.y, 0.f);
        }
        uint32_t hw, lw; split2(v0, v1, hw, lw);
        int addr = row * 128 + (cp ^ ((row & 7) << 2));
        hp_hi[addr] = hw; hp_lo[addr] = lw;
    }
    // (visibility to first gemm's A-reads is ordered by the barrier inside gemm256 ks=0)

    float acc[8][4];

    // ---- layers g2, g3: gemm + bias/relu/split back to hp ----
#pragma unroll 1
    for (int L = 0; L < 2; L++) {
#pragma unroll
        for (int t8 = 0; t8 < 8; t8++)
#pragma unroll
            for (int r = 0; r < 4; r++) acc[t8][r] = 0.f;
        gemm256(hp_hi, hp_lo, wsm4, Whi + L * 32768, Wlo + L * 32768,
                acc, tid, wm, wn, lane);
        const float* bs = bias + L * 256;
        {
            int row = wm * 16 + group;
            int sw = (row & 7) << 2;
            int sw8 = ((row + 8) & 7) << 2;
#pragma unroll
            for (int t8 = 0; t8 < 8; t8++) {
                int colp = wn * 32 + t8 * 4 + tig;
                float2 bv = *(const float2*)(bs + 2 * colp);
                float v0 = fmaxf(acc[t8][0] + bv.x, 0.f);
                float v1 = fmaxf(acc[t8][1] + bv.y, 0.f);
                float v2 = fmaxf(acc[t8][2] + bv.x, 0.f);
                float v3 = fmaxf(acc[t8][3] + bv.y, 0.f);
                uint32_t hw, lw;
                split2(v0, v1, hw, lw);
                int a0 = row * 128 + (colp ^ sw);
                hp_hi[a0] = hw; hp_lo[a0] = lw;
                split2(v2, v3, hw, lw);
                int a1 = (row + 8) * 128 + (colp ^ sw8);
                hp_hi[a1] = hw; hp_lo[a1] = lw;
            }
        }
        // next gemm's first barrier orders these writes vs reads
    }

    // ---- layer g4: gemm + masked pair-sum accumulation ----
#pragma unroll
    for (int t8 = 0; t8 < 8; t8++)
#pragma unroll
        for (int r = 0; r < 4; r++) acc[t8][r] = 0.f;
    gemm256(hp_hi, hp_lo, wsm4, Whi + 2 * 32768, Wlo + 2 * 32768,
            acc, tid, wm, wn, lane);
    {
        float accn[16];
#pragma unroll
        for (int j = 0; j < 16; j++) accn[j] = 0.f;
        const float* bs = bias + 512;
        int row = wm * 16 + group;
        int gr0 = tile * 32 + row, gr1 = gr0 + 8;
#pragma unroll
        for (int t8 = 0; t8 < 8; t8++) {
            float2 bv = *(const float2*)(bs + 2 * (wn * 32 + t8 * 4 + tig));
            if (gr0 < 625) {
                accn[t8 * 2]     += fmaxf(acc[t8][0] + bv.x, 0.f);
                accn[t8 * 2 + 1] += fmaxf(acc[t8][1] + bv.y, 0.f);
            }
            if (gr1 < 625) {
                accn[t8 * 2]     += fmaxf(acc[t8][2] + bv.x, 0.f);
                accn[t8 * 2 + 1] += fmaxf(acc[t8][3] + bv.y, 0.f);
            }
        }
        // reduce over the 8 groups (lane bits 2-4)
#pragma unroll
        for (int off = 4; off <= 16; off <<= 1)
#pragma unroll
            for (int j = 0; j < 16; j++)
                accn[j] += __shfl_down_sync(0xffffffffu, accn[j], off);
        if (lane < 4) {
#pragma unroll
            for (int j = 0; j < 16; j++) red[w * 64 + lane * 16 + j] = accn[j];
        }
    }
    __syncthreads();
    {   // thread tid owns output column n = tid; sum the two wm halves (disjoint rows)
        int n = tid;
        int wn2 = n >> 6, t8o = (n >> 3) & 7, tigo = (n >> 1) & 3, p = n & 1;
        int idx = tigo * 16 + t8o * 2 + p;
        float s = red[(0 * 4 + wn2) * 64 + idx] + red[(1 * 4 + wn2) * 64 + idx];
        xg[((size_t)tile * NB + b) * NH + n] = s;
    }
}

// ---------------- f-MLP + log-softmax ----------------
__global__ void fmlp(const float* __restrict__ xg,
                     const float* __restrict__ f1w, const float* __restrict__ f1b,
                     const float* __restrict__ fc2w, const float* __restrict__ fc2b,
                     const float* __restrict__ fc3w, const float* __restrict__ fc3b,
                     float* __restrict__ out)
{
    int b = blockIdx.x, n = threadIdx.x;
    __shared__ float xs[NH], hs[NH];
    __shared__ float logits[10];
    float v = 0.f;
#pragma unroll
    for (int p = 0; p < NT; p++) v += xg[((size_t)p * NB + b) * NH + n];
    xs[n] = v;
    __syncthreads();

    float acc = f1b[n];
    {
        const float4* wr = (const float4*)(f1w + (size_t)n * NH);
#pragma unroll 8
        for (int k4 = 0; k4 < NH / 4; k4++) {
            float4 w4 = wr[k4];
            const float* xp = &xs[k4 * 4];
            acc = fmaf(xp[0], w4.x, acc); acc = fmaf(xp[1], w4.y, acc);
            acc = fmaf(xp[2], w4.z, acc); acc = fmaf(xp[3], w4.w, acc);
        }
    }
    hs[n] = fmaxf(acc, 0.f);
    __syncthreads();

    acc = fc2b[n];
    {
        const float4* wr = (const float4*)(fc2w + (size_t)n * NH);
#pragma unroll 8
        for (int k4 = 0; k4 < NH / 4; k4++) {
            float4 w4 = wr[k4];
            const float* xp = &hs[k4 * 4];
            acc = fmaf(xp[0], w4.x, acc); acc = fmaf(xp[1], w4.y, acc);
            acc = fmaf(xp[2], w4.z, acc); acc = fmaf(xp[3], w4.w, acc);
        }
    }
    __syncthreads();
    xs[n] = fmaxf(acc, 0.f);
    __syncthreads();

    if (n < 10) {
        float a = fc3b[n];
        const float* w3 = fc3w + n * NH;
#pragma unroll 8
        for (int k = 0; k < NH; k++) a = fmaf(xs[k], w3[k], a);
        logits[n] = a;
    }
    __syncthreads();
    if (n == 0) {
        float m = logits[0];
#pragma unroll
        for (int j = 1; j < 10; j++) m = fmaxf(m, logits[j]);
        float se = 0.f;
#pragma unroll
        for (int j = 0; j < 10; j++) se += expf(logits[j] - m);
        float lse = m + logf(se);
#pragma unroll
        for (int j = 0; j < 10; j++) out[b * 10 + j] = logits[j] - lse;
    }
}

// ---------------- host launch ----------------
extern "C" void kernel_launch(void* const* d_in, const int* in_sizes, int n_in,
                              void* d_out, int out_size)
{
    const float* img = (const float*)d_in[0];
    const float* qst = (const float*)d_in[1];
    const float* cw[4] = {(const float*)d_in[2], (const float*)d_in[6],
                          (const float*)d_in[10], (const float*)d_in[14]};
    const float* cb[4] = {(const float*)d_in[3], (const float*)d_in[7],
                          (const float*)d_in[11], (const float*)d_in[15]};
    const float* bg[4] = {(const float*)d_in[4], (const float*)d_in[8],
                          (const float*)d_in[12], (const float*)d_in[16]};
    const float* bb[4] = {(const float*)d_in[5], (const float*)d_in[9],
                          (const float*)d_in[13], (const float*)d_in[17]};
    const float* g1w = (const float*)d_in[18]; const float* g1b = (const float*)d_in[19];
    const float* g2w = (const float*)d_in[20]; const float* g2b = (const float*)d_in[21];
    const float* g3w = (const float*)d_in[22]; const float* g3b = (const float*)d_in[23];
    const float* g4w = (const float*)d_in[24]; const float* g4b = (const float*)d_in[25];
    const float* f1w = (const float*)d_in[26]; const float* f1b = (const float*)d_in[27];
    const float* fc2w = (const float*)d_in[28]; const float* fc2b = (const float*)d_in[29];
    const float* fc3w = (const float*)d_in[30]; const float* fc3b = (const float*)d_in[31];
    float* out = (float*)d_out;

    float *y1, *y2, *y3, *y4, *sc, *sh, *Ap, *Bp, *Cp, *xg, *bnp;
    uint32_t *whi, *wlo;
    cudaGetSymbolAddress((void**)&y1, g_y1);
    cudaGetSymbolAddress((void**)&y2, g_y2);
    cudaGetSymbolAddress((void**)&y3, g_y3);
    cudaGetSymbolAddress((void**)&y4, g_y4);
    cudaGetSymbolAddress((void**)&sc, g_scale);
    cudaGetSymbolAddress((void**)&sh, g_shift);
    cudaGetSymbolAddress((void**)&bnp, g_bnp);
    cudaGetSymbolAddress((void**)&Ap, g_A);
    cudaGetSymbolAddress((void**)&Bp, g_Bt);
    cudaGetSymbolAddress((void**)&Cp, g_Ct);
    cudaGetSymbolAddress((void**)&xg, g_xg);
    cudaGetSymbolAddress((void**)&whi, g_whi);
    cudaGetSymbolAddress((void**)&wlo, g_wlo);

    cudaFuncSetAttribute(gmlp_mma, cudaFuncAttributeMaxDynamicSharedMemorySize, GMLP_SMEM);

    // [0] weight presplit, [1] C-term (input-only deps)
    wsplit<<<(3 * 32768 + 255) / 256, 256>>>(g2w, g3w, g4w, whi, wlo);
    c_term<<<NB, 256>>>(qst, g1w, g1b, Cp);

    // [2] conv1
    conv_bn_relu_w2<3, false><<<(NB * 40 * 20 + 255) / 256, 256>>>(img, cw[0], cb[0], nullptr, nullptr, y1, 80, 40);

    dim3 bgrd(24, 32);
    bn_part<<<bgrd, 256>>>(y1, bnp, 1600);
    bn_fin<<<24, 32>>>(bnp, bg[0], bb[0], sc + 0, sh + 0, 1600);
    conv_bn_relu_w2<24, true><<<(NB * 20 * 10 + 255) / 256, 256>>>(y1, cw[1], cb[1], sc + 0, sh + 0, y2, 40, 20);
    bn_part<<<bgrd, 256>>>(y2, bnp, 400);
    bn_fin<<<24, 32>>>(bnp, bg[1], bb[1], sc + 24, sh + 24, 400);
    conv_bn_relu_w2<24, true><<<(NB * 10 * 5 + 63) / 64, 64>>>(y2, cw[2], cb[2], sc + 24, sh + 24, y3, 20, 10);
    bn_part<<<bgrd, 256>>>(y3, bnp, 100);
    bn_fin<<<24, 32>>>(bnp, bg[2], bb[2], sc + 48, sh + 48, 100);
    conv_bn_relu<24, true><<<(NB * 5 * 5 + 63) / 64, 64>>>(y3, cw[3], cb[3], sc + 48, sh + 48, y4, 10, 5);
    bn_part<<<bgrd, 256>>>(y4, bnp, 25);
    bn_fin<<<24, 32>>>(bnp, bg[3], bb[3], sc + 72, sh + 72, 25);

    ab_terms<<<NB * 25, 256>>>(y4, sc + 72, sh + 72, g1w, Ap, Bp);

    gmlp_mma<<<NB * NT, 256, GMLP_SMEM>>>(Ap, Bp, Cp, whi, wlo, g2b, g3b, g4b, xg);

    fmlp<<<NB, 256>>>(xg, f1w, f1b, fc2w, fc2b, fc3w, fc3b, out);
}

// round 15
// speedup vs baseline: 1.3158x; 1.3158x over previous
#include <cuda_runtime.h>
#include <cuda_bf16.h>
#include <math.h>
#include <stdint.h>

static constexpr int NB = 512;   // batch
static constexpr int NC = 24;    // conv channels (FS)
static constexpr int NH = 256;   // hidden

// ---------------- scratch (device globals; allocation is forbidden) ----------------
__device__ float g_y1[(size_t)NB * NC * 40 * 40];
__device__ float g_y2[(size_t)NB * NC * 20 * 20];
__device__ float g_y3[(size_t)NB * NC * 10 * 10];
__device__ float g_y4[(size_t)NB * NC * 5 * 5];
__device__ float g_scale[4 * NC];
__device__ float g_shift[4 * NC];
__device__ float g_bnp[24 * 32 * 2];                 // fp32 partial sums (fixed-order, deterministic)
__device__ float g_A[(size_t)NB * 25 * NH];          // W1[:,0:26]  @ obj_i
__device__ float g_Bt[(size_t)NB * 25 * NH];         // W1[:,26:52] @ obj_k
__device__ float g_Ct[(size_t)NB * NH];              // W1[:,52:63] @ q + b1
__device__ float g_xg[(size_t)10 * NB * NH];         // per-tile pair-sum partials
__device__ __align__(16) uint32_t g_whi[3 * 32768];  // weights bf16-hi pairs, [L][ks][n][j]
__device__ __align__(16) uint32_t g_wlo[3 * 32768];  // bf16-lo pairs

// ---------------- helpers ----------------
__device__ __forceinline__ void split2(float v0, float v1, uint32_t& hw, uint32_t& lw) {
    __nv_bfloat16 h0 = __float2bfloat16(v0), h1 = __float2bfloat16(v1);
    float l0 = v0 - __bfloat162float(h0);
    float l1 = v1 - __bfloat162float(h1);
    __nv_bfloat16 e0 = __float2bfloat16(l0), e1 = __float2bfloat16(l1);
    hw = (uint32_t)__bfloat16_as_ushort(h0) | ((uint32_t)__bfloat16_as_ushort(h1) << 16);
    lw = (uint32_t)__bfloat16_as_ushort(e0) | ((uint32_t)__bfloat16_as_ushort(e1) << 16);
}

__device__ __forceinline__ void mma16816(float* c, const uint32_t* a, uint32_t b0, uint32_t b1) {
    asm volatile("mma.sync.aligned.m16n8k16.row.col.f32.bf16.bf16.f32 "
                 "{%0,%1,%2,%3}, {%4,%5,%6,%7}, {%8,%9}, {%0,%1,%2,%3};\n"
                 : "+f"(c[0]), "+f"(c[1]), "+f"(c[2]), "+f"(c[3])
                 : "r"(a[0]), "r"(a[1]), "r"(a[2]), "r"(a[3]), "r"(b0), "r"(b1));
}

__device__ __forceinline__ uint32_t cvta_s(const void* p) {
    return (uint32_t)__cvta_generic_to_shared(p);
}

__device__ __forceinline__ void ldsm4(uint32_t* r, uint32_t a) {
    asm volatile("ldmatrix.sync.aligned.m8n8.x4.shared.b16 {%0,%1,%2,%3}, [%4];"
                 : "=r"(r[0]), "=r"(r[1]), "=r"(r[2]), "=r"(r[3]) : "r"(a));
}

// ---------------- conv1 (+ wsplit + c_term) front kernel ----------------
// Block ranges: [0,1600) conv1 (3->24ch, 80->40, w2), [1600,1984) weight presplit,
// [1984,2496) C-term. All grids exact.
__global__ __launch_bounds__(256) void k_front(
    const float* __restrict__ img, const float* __restrict__ cw1, const float* __restrict__ cb1,
    const float* __restrict__ g2w, const float* __restrict__ g3w, const float* __restrict__ g4w,
    uint32_t* __restrict__ Whi, uint32_t* __restrict__ Wlo,
    const float* __restrict__ qst, const float* __restrict__ g1w, const float* __restrict__ g1b,
    float* __restrict__ Cm, float* __restrict__ y1)
{
    int bid = blockIdx.x;
    int tid = threadIdx.x;
    if (bid >= 1600) {
        if (bid < 1600 + 384) {
            int q = (bid - 1600) * 256 + tid;   // exactly 3*32768
            int L = q >> 15, r = q & 32767;
            int n = r >> 7, k2 = r & 127;
            const float* src = (L == 0) ? g2w : (L == 1) ? g3w : g4w;
            float2 v = *(const float2*)(src + (size_t)n * 256 + 2 * k2);
            uint32_t hw, lw;
            split2(v.x, v.y, hw, lw);
            int dst = L * 32768 + (k2 >> 3) * 2048 + n * 8 + (k2 & 7);
            Whi[dst] = hw; Wlo[dst] = lw;
        } else {
            int b = bid - (1600 + 384);
            float acc = g1b[tid];
            const float* wr = g1w + tid * 63 + 52;
#pragma unroll
            for (int j = 0; j < 11; j++) acc = fmaf(qst[j * NB + b], wr[j], acc);
            Cm[(size_t)b * NH + tid] = acc;
        }
        return;
    }

    // ---- conv1 body (CIN=3, no BN fold), 2 output px / thread ----
    constexpr int CIN = 3;
    const int Hin = 80, Hout = 40;
    __shared__ float wsm[CIN * 9 * NC];
    __shared__ float bsm[NC];
    for (int t = tid; t < CIN * 9 * NC; t += 256) {
        int c = t % NC, rest = t / NC;
        wsm[t] = cw1[c * CIN * 9 + rest];
    }
    if (tid < NC) bsm[tid] = cb1[tid];
    __syncthreads();

    int W2 = Hout >> 1;
    int tix = bid * 256 + tid;            // NB*Hout*W2 = 409600 = 1600*256 exactly
    int gx = tix % W2;
    int t2 = tix / W2;
    int oh = t2 % Hout;
    int b  = t2 / Hout;
    int ow0  = gx * 2;
    int col0 = 4 * gx - 1;

    float acc0[NC], acc1[NC];
#pragma unroll
    for (int c = 0; c < NC; c++) { acc0[c] = bsm[c]; acc1[c] = bsm[c]; }

    const float* xb = img + (size_t)b * CIN * Hin * Hin;
    for (int ci = 0; ci < CIN; ci++) {
        const float* xc = xb + (size_t)ci * Hin * Hin;
#pragma unroll
        for (int r = 0; r < 3; r++) {
            int ih = 2 * oh - 1 + r;
            float v[5];
            if ((unsigned)ih < (unsigned)Hin) {
                const float* xr = xc + ih * Hin;
                float4 v4 = *(const float4*)(xr + col0 + 1);
                v[0] = (gx > 0) ? xr[col0] : 0.f;
                v[1] = v4.x; v[2] = v4.y; v[3] = v4.z; v[4] = v4.w;
            } else {
                v[0] = v[1] = v[2] = v[3] = v[4] = 0.f;
            }
#pragma unroll
            for (int s = 0; s < 3; s++) {
                float p0 = v[s];
                float p1 = v[s + 2];
                const float4* wp4 = (const float4*)&wsm[(ci * 9 + r * 3 + s) * NC];
#pragma unroll
                for (int q = 0; q < 6; q++) {
                    float4 w4 = wp4[q];
                    acc0[4*q+0] = fmaf(p0, w4.x, acc0[4*q+0]);
                    acc0[4*q+1] = fmaf(p0, w4.y, acc0[4*q+1]);
                    acc0[4*q+2] = fmaf(p0, w4.z, acc0[4*q+2]);
                    acc0[4*q+3] = fmaf(p0, w4.w, acc0[4*q+3]);
                    acc1[4*q+0] = fmaf(p1, w4.x, acc1[4*q+0]);
                    acc1[4*q+1] = fmaf(p1, w4.y, acc1[4*q+1]);
                    acc1[4*q+2] = fmaf(p1, w4.z, acc1[4*q+2]);
                    acc1[4*q+3] = fmaf(p1, w4.w, acc1[4*q+3]);
                }
            }
        }
    }
    int HW = Hout * Hout;
    float* yb = y1 + (size_t)b * NC * HW + oh * Hout + ow0;
#pragma unroll
    for (int c = 0; c < NC; c++) {
        float2 o = make_float2(fmaxf(acc0[c], 0.f), fmaxf(acc1[c], 0.f));
        *(float2*)(yb + (size_t)c * HW) = o;
    }
}

// ---------------- conv (stride 2, pad 1) + bias + relu, 2 output px / thread ----------------
template <int CIN, bool AFFINE>
__global__ void conv_bn_relu_w2(
    const float* __restrict__ x, const float* __restrict__ w,
    const float* __restrict__ bias,
    const float* __restrict__ scl, const float* __restrict__ shf,
    float* __restrict__ y, int Hin, int Hout)
{
    __shared__ float wsm[CIN * 9 * NC];   // [ci][r][s][c]
    __shared__ float bsm[NC];
    __shared__ float ssm[CIN], hsm[CIN];
    for (int t = threadIdx.x; t < CIN * 9 * NC; t += blockDim.x) {
        int c = t % NC, rest = t / NC;
        wsm[t] = w[c * CIN * 9 + rest];
    }
    if (threadIdx.x < NC && threadIdx.x < blockDim.x) bsm[threadIdx.x] = bias[threadIdx.x];
    if (threadIdx.x < CIN) {
        ssm[threadIdx.x] = AFFINE ? scl[threadIdx.x] : 1.f;
        hsm[threadIdx.x] = AFFINE ? shf[threadIdx.x] : 0.f;
    }
    __syncthreads();

    int W2 = Hout >> 1;
    int tix = blockIdx.x * blockDim.x + threadIdx.x;   // over NB*Hout*W2
    if (tix >= NB * Hout * W2) return;
    int gx = tix % W2;
    int t2 = tix / W2;
    int oh = t2 % Hout;
    int b  = t2 / Hout;
    int ow0  = gx * 2;
    int col0 = 4 * gx - 1;

    float acc0[NC], acc1[NC];
#pragma unroll
    for (int c = 0; c < NC; c++) { acc0[c] = bsm[c]; acc1[c] = bsm[c]; }

    const float* xb = x + (size_t)b * CIN * Hin * Hin;
    for (int ci = 0; ci < CIN; ci++) {
        const float* xc = xb + (size_t)ci * Hin * Hin;
        float a = ssm[ci], sh = hsm[ci];
#pragma unroll
        for (int r = 0; r < 3; r++) {
            int ih = 2 * oh - 1 + r;
            float v[5];
            if ((unsigned)ih < (unsigned)Hin) {
                const float* xr = xc + ih * Hin;
                float4 v4 = *(const float4*)(xr + col0 + 1);
                v[0] = (gx > 0) ? fmaf(xr[col0], a, sh) : 0.f;   // pad col -1 -> 0
                v[1] = fmaf(v4.x, a, sh);
                v[2] = fmaf(v4.y, a, sh);
                v[3] = fmaf(v4.z, a, sh);
                v[4] = fmaf(v4.w, a, sh);
            } else {
                v[0] = v[1] = v[2] = v[3] = v[4] = 0.f;
            }
#pragma unroll
            for (int s = 0; s < 3; s++) {
                float p0 = v[s];
                float p1 = v[s + 2];
                const float4* wp4 = (const float4*)&wsm[(ci * 9 + r * 3 + s) * NC];
#pragma unroll
                for (int q = 0; q < 6; q++) {
                    float4 w4 = wp4[q];
                    acc0[4*q+0] = fmaf(p0, w4.x, acc0[4*q+0]);
                    acc0[4*q+1] = fmaf(p0, w4.y, acc0[4*q+1]);
                    acc0[4*q+2] = fmaf(p0, w4.z, acc0[4*q+2]);
                    acc0[4*q+3] = fmaf(p0, w4.w, acc0[4*q+3]);
                    acc1[4*q+0] = fmaf(p1, w4.x, acc1[4*q+0]);
                    acc1[4*q+1] = fmaf(p1, w4.y, acc1[4*q+1]);
                    acc1[4*q+2] = fmaf(p1, w4.z, acc1[4*q+2]);
                    acc1[4*q+3] = fmaf(p1, w4.w, acc1[4*q+3]);
                }
            }
        }
    }
    int HW = Hout * Hout;
    float* yb = y + (size_t)b * NC * HW + oh * Hout + ow0;
#pragma unroll
    for (int c = 0; c < NC; c++) {
        float2 o = make_float2(fmaxf(acc0[c], 0.f), fmaxf(acc1[c], 0.f));
        *(float2*)(yb + (size_t)c * HW) = o;
    }
}

// ---------------- scalar conv (used for conv4, Hout=5 odd) ----------------
template <int CIN, bool AFFINE>
__global__ void conv_bn_relu(const float* __restrict__ x, const float* __restrict__ w,
                             const float* __restrict__ bias,
                             const float* __restrict__ scl, const float* __restrict__ shf,
                             float* __restrict__ y, int Hin, int Hout)
{
    __shared__ float wsm[CIN * 9 * NC];
    __shared__ float bsm[NC];
    __shared__ float ssm[CIN], hsm[CIN];
    for (int t = threadIdx.x; t < CIN * 9 * NC; t += blockDim.x) {
        int c = t % NC, rest = t / NC;
        wsm[t] = w[c * CIN * 9 + rest];
    }
    if (threadIdx.x < NC) bsm[threadIdx.x] = bias[threadIdx.x];
    if (threadIdx.x < CIN) {
        ssm[threadIdx.x] = AFFINE ? scl[threadIdx.x] : 1.f;
        hsm[threadIdx.x] = AFFINE ? shf[threadIdx.x] : 0.f;
    }
    __syncthreads();

    int pix = blockIdx.x * blockDim.x + threadIdx.x;
    if (pix >= NB * Hout * Hout) return;
    int ow = pix % Hout;
    int t2 = pix / Hout;
    int oh = t2 % Hout;
    int b  = t2 / Hout;

    float acc[NC];
#pragma unroll
    for (int c = 0; c < NC; c++) acc[c] = bsm[c];

    const float* xb = x + (size_t)b * CIN * Hin * Hin;
    for (int ci = 0; ci < CIN; ci++) {
        const float* xc = xb + (size_t)ci * Hin * Hin;
        float a = ssm[ci], sh = hsm[ci];
#pragma unroll
        for (int r = 0; r < 3; r++) {
            int ih = 2 * oh - 1 + r;
            if ((unsigned)ih >= (unsigned)Hin) continue;
#pragma unroll
            for (int s = 0; s < 3; s++) {
                int iw = 2 * ow - 1 + s;
                if ((unsigned)iw >= (unsigned)Hin) continue;
                float v = fmaf(xc[ih * Hin + iw], a, sh);
                const float4* wp4 = (const float4*)&wsm[(ci * 9 + r * 3 + s) * NC];
#pragma unroll
                for (int q = 0; q < 6; q++) {
                    float4 w4 = wp4[q];
                    acc[4*q+0] = fmaf(v, w4.x, acc[4*q+0]);
                    acc[4*q+1] = fmaf(v, w4.y, acc[4*q+1]);
                    acc[4*q+2] = fmaf(v, w4.z, acc[4*q+2]);
                    acc[4*q+3] = fmaf(v, w4.w, acc[4*q+3]);
                }
            }
        }
    }
    float* yb = y + (size_t)b * NC * Hout * Hout + oh * Hout + ow;
    int HW = Hout * Hout;
#pragma unroll
    for (int c = 0; c < NC; c++) yb[(size_t)c * HW] = fmaxf(acc[c], 0.f);
}

// ---------------- BN stats: two-stage, fp32 accumulation (fixed order, deterministic) ------
__global__ void bn_part(const float* __restrict__ y, float* __restrict__ part, int HW)
{
    int c = blockIdx.x, s = blockIdx.y;
    float sum = 0.f, sq = 0.f;
    if ((HW & 3) == 0) {
        int HW4 = HW >> 2;
        for (int b = s * 16; b < s * 16 + 16; b++) {
            const float4* p = (const float4*)(y + ((size_t)b * NC + c) * HW);
            for (int i = threadIdx.x; i < HW4; i += 256) {
                float4 v = p[i];
                sum += (v.x + v.y) + (v.z + v.w);
                float q2 = fmaf(v.x, v.x, v.y * v.y);
                float q3 = fmaf(v.z, v.z, v.w * v.w);
                sq += q2 + q3;
            }
        }
    } else {
        for (int b = s * 16; b < s * 16 + 16; b++) {
            const float* p = y + ((size_t)b * NC + c) * HW;
            for (int hw = threadIdx.x; hw < HW; hw += 256) {
                float v = p[hw];
                sum += v;
                sq = fmaf(v, v, sq);
            }
        }
    }
    __shared__ float rs[256], rq[256];
    rs[threadIdx.x] = sum; rq[threadIdx.x] = sq;
    __syncthreads();
    for (int off = 128; off; off >>= 1) {
        if (threadIdx.x < off) { rs[threadIdx.x] += rs[threadIdx.x + off];
                                 rq[threadIdx.x] += rq[threadIdx.x + off]; }
        __syncthreads();
    }
    if (threadIdx.x == 0) {
        part[(c * 32 + s) * 2 + 0] = rs[0];
        part[(c * 32 + s) * 2 + 1] = rq[0];
    }
}

__global__ void bn_fin(const float* __restrict__ part,
                       const float* __restrict__ gamma, const float* __restrict__ beta,
                       float* __restrict__ scale, float* __restrict__ shift, int HW)
{
    int c = blockIdx.x, l = threadIdx.x;   // 32 threads
    double s = (double)part[(c * 32 + l) * 2 + 0];
    double q = (double)part[(c * 32 + l) * 2 + 1];
#pragma unroll
    for (int off = 16; off; off >>= 1) {
        s += __shfl_down_sync(0xffffffffu, s, off);
        q += __shfl_down_sync(0xffffffffu, q, off);
    }
    if (l == 0) {
        double n = (double)NB * HW;
        double mean = s / n;
        double var  = q / n - mean * mean;
        float inv = gamma[c] * rsqrtf((float)var + 1e-5f);
        scale[c] = inv;
        shift[c] = beta[c] - (float)mean * inv;
    }
}

// ---------------- layer-1 factorization terms ----------------
__global__ void ab_terms(const float* __restrict__ y4,
                         const float* __restrict__ scl, const float* __restrict__ shf,
                         const float* __restrict__ g1w,
                         float* __restrict__ A, float* __restrict__ Bm)
{
    int bi = blockIdx.x;            // b*25+i
    int i  = bi % 25;
    int b  = bi / 25;
    __shared__ float obj[26];
    if (threadIdx.x < NC) {
        float v = y4[((size_t)b * NC + threadIdx.x) * 25 + i];
        obj[threadIdx.x] = fmaf(v, scl[threadIdx.x], shf[threadIdx.x]);
    }
    if (threadIdx.x == 24) obj[24] = (float)(i / 5 - 2) * 0.5f;
    if (threadIdx.x == 25) obj[25] = (float)(i % 5 - 2) * 0.5f;
    __syncthreads();
    int n = threadIdx.x;
    const float* wr = g1w + n * 63;
    float a = 0.f, bb = 0.f;
#pragma unroll
    for (int c = 0; c < 26; c++) {
        float o = obj[c];
        a  = fmaf(o, wr[c],      a);
        bb = fmaf(o, wr[26 + c], bb);
    }
    A [(size_t)bi * NH + n] = a;
    Bm[(size_t)bi * NH + n] = bb;
}

// ---------------- fused g-MLP on tensor cores (bf16 hi/lo split, fp32 acc) ----------------
// M=64 tile, 2 CTAs/SM (confirmed-best R10/R13 configuration).
// SMEM u32 layout:
//   [0,8192)       hp_hi : h bf16-hi pairs, [row 64][col 128] col ^= (row&7)<<2
//   [8192,16384)   hp_lo
//   [16384,24576)  wsm   : 2 bufs x 16KB; per buf (uint4): hi [j2*256+n] at [0,512), lo [512,1024)
//   [24576,25344)  bias  : 3 x 256 f32
//   [25344,25600)  Cs
//   [25600,26112)  red
static constexpr int GMLP_SMEM = 26112 * 4;   // 104448 B

__device__ __forceinline__ void gemm256(
    uint32_t* __restrict__ hp_hi, uint32_t* __restrict__ hp_lo, uint4* __restrict__ wsm4,
    const uint32_t* __restrict__ wh, const uint32_t* __restrict__ wl,
    float acc[2][8][4], int tid, int wm, int wn, int lane)
{
    // thread tid owns weight row n = tid; 8 k-pairs per k-step (2 uint4 each of hi/lo)
    const uint4* wh4 = (const uint4*)wh;
    const uint4* wl4 = (const uint4*)wl;
    uint4 ph0 = wh4[tid * 2],     ph1 = wh4[tid * 2 + 1];
    uint4 pl0 = wl4[tid * 2],     pl1 = wl4[tid * 2 + 1];

    // per-lane LDSM address components
    int mat = lane >> 3, rr = lane & 7;
    int m2 = mat >> 1;                     // k-half of the A matrix this lane addresses
    uint32_t a_hi_base[2], a_lo_base[2];
#pragma unroll
    for (int mi = 0; mi < 2; mi++) {
        int rowA = wm * 32 + mi * 16 + (mat & 1) * 8 + rr;
        a_hi_base[mi] = cvta_s(hp_hi) + rowA * 512;   // 128 u32 = 512 B per row
        a_lo_base[mi] = cvta_s(hp_lo) + rowA * 512;
    }
    int j2b = (lane >> 3) & 1, nbq = lane >> 4, rb = lane & 7;
    uint32_t b_off[4];
#pragma unroll
    for (int q = 0; q < 4; q++) {
        int nb = wn * 8 + 2 * q + nbq;
        b_off[q] = (uint32_t)(j2b * 256 + nb * 8 + rb) * 16;   // bytes within buffer
    }
    uint32_t wbase = cvta_s(wsm4);

#pragma unroll 1
    for (int ks = 0; ks < 16; ks++) {
        uint4* wb = wsm4 + (ks & 1) * 1024;
        wb[        tid] = ph0;     // hi, j2=0
        wb[ 256 + tid] = ph1;      // hi, j2=1
        wb[ 512 + tid] = pl0;      // lo, j2=0
        wb[ 768 + tid] = pl1;      // lo, j2=1
        __syncthreads();
        if (ks < 15) {
            ph0 = wh4[(ks + 1) * 512 + tid * 2]; ph1 = wh4[(ks + 1) * 512 + tid * 2 + 1];
            pl0 = wl4[(ks + 1) * 512 + tid * 2]; pl1 = wl4[(ks + 1) * 512 + tid * 2 + 1];
        }
        // A fragments via ldmatrix (unit index = (ks*2 + m2) ^ rr, 16B units)
        uint32_t ahi[2][4], alo[2][4];
#pragma unroll
        for (int mi = 0; mi < 2; mi++) {
            uint32_t un = (uint32_t)(((ks * 2 + m2) ^ rr) * 16);
            ldsm4(ahi[mi], a_hi_base[mi] + un);
            ldsm4(alo[mi], a_lo_base[mi] + un);
        }
        uint32_t bufb = wbase + (uint32_t)(ks & 1) * 16384;
#pragma unroll
        for (int q = 0; q < 4; q++) {
            uint32_t bh[4], bl[4];
            ldsm4(bh, bufb + b_off[q]);            // (b0,b1) of n-blocks 2q, 2q+1 (hi)
            ldsm4(bl, bufb + 8192 + b_off[q]);     // same (lo)
#pragma unroll
            for (int mi = 0; mi < 2; mi++) {
                mma16816(acc[mi][2 * q],     ahi[mi], bh[0], bh[1]);
                mma16816(acc[mi][2 * q],     ahi[mi], bl[0], bl[1]);
                mma16816(acc[mi][2 * q],     alo[mi], bh[0], bh[1]);
                mma16816(acc[mi][2 * q + 1], ahi[mi], bh[2], bh[3]);
                mma16816(acc[mi][2 * q + 1], ahi[mi], bl[2], bl[3]);
                mma16816(acc[mi][2 * q + 1], alo[mi], bh[2], bh[3]);
            }
        }
    }
    __syncthreads();   // all hp reads complete -> safe to overwrite hp
}

__global__ __launch_bounds__(256, 2) void gmlp_mma(
    const float* __restrict__ A, const float* __restrict__ Bm, const float* __restrict__ Cm,
    const uint32_t* __restrict__ Whi, const uint32_t* __restrict__ Wlo,
    const float* __restrict__ g2b, const float* __restrict__ g3b, const float* __restrict__ g4b,
    float* __restrict__ xg)
{
    extern __shared__ uint32_t smu[];
    uint32_t* hp_hi = smu;
    uint32_t* hp_lo = smu + 8192;
    uint4*    wsm4  = (uint4*)(smu + 16384);
    float* bias = (float*)(smu + 24576);
    float* Cs   = (float*)(smu + 25344);
    float* red  = (float*)(smu + 25600);

    int tid = threadIdx.x;
    int lane = tid & 31, w = tid >> 5;
    int wm = w >> 2, wn = w & 3;
    int group = lane >> 2, tig = lane & 3;
    int b = blockIdx.x / 10;
    int tile = blockIdx.x % 10;

    bias[tid] = g2b[tid]; bias[256 + tid] = g3b[tid]; bias[512 + tid] = g4b[tid];
    Cs[tid] = Cm[(size_t)b * NH + tid];
    __syncthreads();

    const float* Ab = A  + (size_t)b * 25 * NH;
    const float* Bb = Bm + (size_t)b * 25 * NH;
    int rhalf = tid >> 7;
    int cp = tid & 127;
#pragma unroll 4
    for (int q0 = 0; q0 < 64; q0 += 2) {
        int row = q0 + rhalf;
        int gr = tile * 64 + row;
        float v0 = 0.f, v1 = 0.f;
        if (gr < 625) {
            int i = gr % 25, k = gr / 25;
            float2 av = *(const float2*)(Ab + i * NH + 2 * cp);
            float2 bv = *(const float2*)(Bb + k * NH + 2 * cp);
            float2 cv = *(const float2*)(Cs + 2 * cp);
            v0 = fmaxf(av.x + bv.x + cv.x, 0.f);
            v1 = fmaxf(av.y + bv.y + cv.y, 0.f);
        }
        uint32_t hw, lw; split2(v0, v1, hw, lw);
        int addr = row * 128 + (cp ^ ((row & 7) << 2));
        hp_hi[addr] = hw; hp_lo[addr] = lw;
    }

    float acc[2][8][4];

#pragma unroll 1
    for (int L = 0; L < 2; L++) {
#pragma unroll
        for (int mi = 0; mi < 2; mi++)
#pragma unroll
            for (int t8 = 0; t8 < 8; t8++)
#pragma unroll
                for (int r = 0; r < 4; r++) acc[mi][t8][r] = 0.f;
        gemm256(hp_hi, hp_lo, wsm4, Whi + L * 32768, Wlo + L * 32768,
                acc, tid, wm, wn, lane);
        const float* bs = bias + L * 256;
#pragma unroll
        for (int mi = 0; mi < 2; mi++) {
            int row = wm * 32 + mi * 16 + group;
            int sw = (row & 7) << 2;
#pragma unroll
            for (int t8 = 0; t8 < 8; t8++) {
                int colp = wn * 32 + t8 * 4 + tig;
                float2 bv = *(const float2*)(bs + 2 * colp);
                float v0 = fmaxf(acc[mi][t8][0] + bv.x, 0.f);
                float v1 = fmaxf(acc[mi][t8][1] + bv.y, 0.f);
                float v2 = fmaxf(acc[mi][t8][2] + bv.x, 0.f);
                float v3 = fmaxf(acc[mi][t8][3] + bv.y, 0.f);
                uint32_t hw, lw;
                split2(v0, v1, hw, lw);
                int a0 = row * 128 + (colp ^ sw);
                hp_hi[a0] = hw; hp_lo[a0] = lw;
                split2(v2, v3, hw, lw);
                int a1 = (row + 8) * 128 + (colp ^ sw);
                hp_hi[a1] = hw; hp_lo[a1] = lw;
            }
        }
    }

#pragma unroll
    for (int mi = 0; mi < 2; mi++)
#pragma unroll
        for (int t8 = 0; t8 < 8; t8++)
#pragma unroll
            for (int r = 0; r < 4; r++) acc[mi][t8][r] = 0.f;
    gemm256(hp_hi, hp_lo, wsm4, Whi + 2 * 32768, Wlo + 2 * 32768,
            acc, tid, wm, wn, lane);
    {
        float accn[16];
#pragma unroll
        for (int j = 0; j < 16; j++) accn[j] = 0.f;
        const float* bs = bias + 512;
#pragma unroll
        for (int mi = 0; mi < 2; mi++) {
            int row = wm * 32 + mi * 16 + group;
            int gr0 = tile * 64 + row, gr1 = gr0 + 8;
#pragma unroll
            for (int t8 = 0; t8 < 8; t8++) {
                float2 bv = *(const float2*)(bs + 2 * (wn * 32 + t8 * 4 + tig));
                if (gr0 < 625) {
                    accn[t8 * 2]     += fmaxf(acc[mi][t8][0] + bv.x, 0.f);
                    accn[t8 * 2 + 1] += fmaxf(acc[mi][t8][1] + bv.y, 0.f);
                }
                if (gr1 < 625) {
                    accn[t8 * 2]     += fmaxf(acc[mi][t8][2] + bv.x, 0.f);
                    accn[t8 * 2 + 1] += fmaxf(acc[mi][t8][3] + bv.y, 0.f);
                }
            }
        }
#pragma unroll
        for (int off = 4; off <= 16; off <<= 1)
#pragma unroll
            for (int j = 0; j < 16; j++)
                accn[j] += __shfl_down_sync(0xffffffffu, accn[j], off);
        if (lane < 4) {
#pragma unroll
            for (int j = 0; j < 16; j++) red[w * 64 + lane * 16 + j] = accn[j];
        }
    }
    __syncthreads();
    {
        int n = tid;
        int wn2 = n >> 6, t8o = (n >> 3) & 7, tigo = (n >> 1) & 3, p = n & 1;
        int idx = tigo * 16 + t8o * 2 + p;
        float s = red[(0 * 4 + wn2) * 64 + idx] + red[(1 * 4 + wn2) * 64 + idx];
        xg[((size_t)tile * NB + b) * NH + n] = s;
    }
}

// ---------------- f-MLP + log-softmax ----------------
__global__ void fmlp(const float* __restrict__ xg,
                     const float* __restrict__ f1w, const float* __restrict__ f1b,
                     const float* __restrict__ fc2w, const float* __restrict__ fc2b,
                     const float* __restrict__ fc3w, const float* __restrict__ fc3b,
                     float* __restrict__ out)
{
    int b = blockIdx.x, n = threadIdx.x;
    __shared__ float xs[NH], hs[NH];
    __shared__ float logits[10];
    float v = 0.f;
#pragma unroll
    for (int p = 0; p < 10; p++) v += xg[((size_t)p * NB + b) * NH + n];
    xs[n] = v;
    __syncthreads();

    float acc = f1b[n];
    {
        const float4* wr = (const float4*)(f1w + (size_t)n * NH);
#pragma unroll 8
        for (int k4 = 0; k4 < NH / 4; k4++) {
            float4 w4 = wr[k4];
            const float* xp = &xs[k4 * 4];
            acc = fmaf(xp[0], w4.x, acc); acc = fmaf(xp[1], w4.y, acc);
            acc = fmaf(xp[2], w4.z, acc); acc = fmaf(xp[3], w4.w, acc);
        }
    }
    hs[n] = fmaxf(acc, 0.f);
    __syncthreads();

    acc = fc2b[n];
    {
        const float4* wr = (const float4*)(fc2w + (size_t)n * NH);
#pragma unroll 8
        for (int k4 = 0; k4 < NH / 4; k4++) {
            float4 w4 = wr[k4];
            const float* xp = &hs[k4 * 4];
            acc = fmaf(xp[0], w4.x, acc); acc = fmaf(xp[1], w4.y, acc);
            acc = fmaf(xp[2], w4.z, acc); acc = fmaf(xp[3], w4.w, acc);
        }
    }
    __syncthreads();
    xs[n] = fmaxf(acc, 0.f);
    __syncthreads();

    if (n < 10) {
        float a = fc3b[n];
        const float* w3 = fc3w + n * NH;
#pragma unroll 8
        for (int k = 0; k < NH; k++) a = fmaf(xs[k], w3[k], a);
        logits[n] = a;
    }
    __syncthreads();
    if (n == 0) {
        float m = logits[0];
#pragma unroll
        for (int j = 1; j < 10; j++) m = fmaxf(m, logits[j]);
        float se = 0.f;
#pragma unroll
        for (int j = 0; j < 10; j++) se += expf(logits[j] - m);
        float lse = m + logf(se);
#pragma unroll
        for (int j = 0; j < 10; j++) out[b * 10 + j] = logits[j] - lse;
    }
}

// ---------------- host launch ----------------
extern "C" void kernel_launch(void* const* d_in, const int* in_sizes, int n_in,
                              void* d_out, int out_size)
{
    const float* img = (const float*)d_in[0];
    const float* qst = (const float*)d_in[1];
    const float* cw[4] = {(const float*)d_in[2], (const float*)d_in[6],
                          (const float*)d_in[10], (const float*)d_in[14]};
    const float* cb[4] = {(const float*)d_in[3], (const float*)d_in[7],
                          (const float*)d_in[11], (const float*)d_in[15]};
    const float* bg[4] = {(const float*)d_in[4], (const float*)d_in[8],
                          (const float*)d_in[12], (const float*)d_in[16]};
    const float* bb[4] = {(const float*)d_in[5], (const float*)d_in[9],
                          (const float*)d_in[13], (const float*)d_in[17]};
    const float* g1w = (const float*)d_in[18]; const float* g1b = (const float*)d_in[19];
    const float* g2w = (const float*)d_in[20]; const float* g2b = (const float*)d_in[21];
    const float* g3w = (const float*)d_in[22]; const float* g3b = (const float*)d_in[23];
    const float* g4w = (const float*)d_in[24]; const float* g4b = (const float*)d_in[25];
    const float* f1w = (const float*)d_in[26]; const float* f1b = (const float*)d_in[27];
    const float* fc2w = (const float*)d_in[28]; const float* fc2b = (const float*)d_in[29];
    const float* fc3w = (const float*)d_in[30]; const float* fc3b = (const float*)d_in[31];
    float* out = (float*)d_out;

    float *y1, *y2, *y3, *y4, *sc, *sh, *Ap, *Bp, *Cp, *xg, *bnp;
    uint32_t *whi, *wlo;
    cudaGetSymbolAddress((void**)&y1, g_y1);
    cudaGetSymbolAddress((void**)&y2, g_y2);
    cudaGetSymbolAddress((void**)&y3, g_y3);
    cudaGetSymbolAddress((void**)&y4, g_y4);
    cudaGetSymbolAddress((void**)&sc, g_scale);
    cudaGetSymbolAddress((void**)&sh, g_shift);
    cudaGetSymbolAddress((void**)&bnp, g_bnp);
    cudaGetSymbolAddress((void**)&Ap, g_A);
    cudaGetSymbolAddress((void**)&Bp, g_Bt);
    cudaGetSymbolAddress((void**)&Cp, g_Ct);
    cudaGetSymbolAddress((void**)&xg, g_xg);
    cudaGetSymbolAddress((void**)&whi, g_whi);
    cudaGetSymbolAddress((void**)&wlo, g_wlo);

    cudaFuncSetAttribute(gmlp_mma, cudaFuncAttributeMaxDynamicSharedMemorySize, GMLP_SMEM);

    // [0] fused front: conv1 | weight presplit | C-term
    k_front<<<1600 + 384 + NB, 256>>>(img, cw[0], cb[0], g2w, g3w, g4w, whi, wlo,
                                      qst, g1w, g1b, Cp, y1);

    dim3 bgrd(24, 32);
    bn_part<<<bgrd, 256>>>(y1, bnp, 1600);
    bn_fin<<<24, 32>>>(bnp, bg[0], bb[0], sc + 0, sh + 0, 1600);
    conv_bn_relu_w2<24, true><<<(NB * 20 * 10 + 255) / 256, 256>>>(y1, cw[1], cb[1], sc + 0, sh + 0, y2, 40, 20);
    bn_part<<<bgrd, 256>>>(y2, bnp, 400);
    bn_fin<<<24, 32>>>(bnp, bg[1], bb[1], sc + 24, sh + 24, 400);
    conv_bn_relu_w2<24, true><<<(NB * 10 * 5 + 63) / 64, 64>>>(y2, cw[2], cb[2], sc + 24, sh + 24, y3, 20, 10);
    bn_part<<<bgrd, 256>>>(y3, bnp, 100);
    bn_fin<<<24, 32>>>(bnp, bg[2], bb[2], sc + 48, sh + 48, 100);
    conv_bn_relu<24, true><<<(NB * 5 * 5 + 63) / 64, 64>>>(y3, cw[3], cb[3], sc + 48, sh + 48, y4, 10, 5);
    bn_part<<<bgrd, 256>>>(y4, bnp, 25);
    bn_fin<<<24, 32>>>(bnp, bg[3], bb[3], sc + 72, sh + 72, 25);

    ab_terms<<<NB * 25, 256>>>(y4, sc + 72, sh + 72, g1w, Ap, Bp);

    gmlp_mma<<<NB * 10, 256, GMLP_SMEM>>>(Ap, Bp, Cp, whi, wlo, g2b, g3b, g4b, xg);

    fmlp<<<NB, 256>>>(xg, f1w, f1b, fc2w, fc2b, fc3w, fc3b, out);
}